// round 15
// baseline (speedup 1.0000x reference)
#include <cuda_runtime.h>
#include <cuda_bf16.h>
#include <math.h>
#include <stdint.h>

#define B_  4
#define M_  1024
#define R_  256
#define H_  16
#define DH_ 64
#define D_  1024   // H_*DH_

// q scale folds 1/sqrt(DH) AND log2(e) (softmax computed in exp2 domain)
#define QSCALE 0.18033688011112042f   // 0.125 * log2(e)

// q,k: bf16 (b,h,m,d) bias+RoPE applied (q prescaled by QSCALE).
// v: f16 (b,h,d,m) TRANSPOSED, NO bias (added exactly in attn epilogue).
__device__ uint4 g_qbf4[(size_t)B_ * H_ * M_ * DH_ / 8];
__device__ uint4 g_kbf4[(size_t)B_ * H_ * M_ * DH_ / 8];
__device__ uint4 g_vT4 [(size_t)B_ * H_ * DH_ * M_ / 8];
// prep buffers: P in bf16, V basis transposed to [d][r] bf16
__device__ uint4 g_Pbf4[(size_t)3 * B_ * M_ * R_ / 8];
__device__ uint4 g_VT4p[(size_t)3 * D_ * R_ / 8];

__device__ __forceinline__ uint32_t smem_u32(const void* p) {
    uint32_t a;
    asm("{ .reg .u64 t; cvta.to.shared.u64 t, %1; cvt.u32.u64 %0, t; }" : "=r"(a) : "l"(p));
    return a;
}
#define SWZ(x) ((x) ^ (((x) >> 3) & 0x70))

#define LDMATRIX_X4(r0, r1, r2, r3, addr) \
    asm volatile("ldmatrix.sync.aligned.m8n8.x4.shared.b16 {%0,%1,%2,%3}, [%4];" \
                 : "=r"(r0), "=r"(r1), "=r"(r2), "=r"(r3) : "r"(addr))

#define MMA_16816(d, a, b0, b1) \
    asm volatile("mma.sync.aligned.m16n8k16.row.col.f32.bf16.bf16.f32 " \
                 "{%0,%1,%2,%3}, {%4,%5,%6,%7}, {%8,%9}, {%0,%1,%2,%3};" \
                 : "+f"((d)[0]), "+f"((d)[1]), "+f"((d)[2]), "+f"((d)[3]) \
                 : "r"((a)[0]), "r"((a)[1]), "r"((a)[2]), "r"((a)[3]), "r"(b0), "r"(b1))

#define MMA_16816_F16(d, a, b0, b1) \
    asm volatile("mma.sync.aligned.m16n8k16.row.col.f32.f16.f16.f32 " \
                 "{%0,%1,%2,%3}, {%4,%5,%6,%7}, {%8,%9}, {%0,%1,%2,%3};" \
                 : "+f"((d)[0]), "+f"((d)[1]), "+f"((d)[2]), "+f"((d)[3]) \
                 : "r"((a)[0]), "r"((a)[1]), "r"((a)[2]), "r"((a)[3]), "r"(b0), "r"(b1))

#define CP_ASYNC16(dst, src) \
    asm volatile("cp.async.cg.shared.global [%0], [%1], 16;" :: "r"(dst), "l"(src))
#define CP_COMMIT()  asm volatile("cp.async.commit_group;" ::: "memory")
#define CP_WAIT(n)   asm volatile("cp.async.wait_group %0;" :: "n"(n) : "memory")

__device__ __forceinline__ uint32_t pack_bf16(float lo, float hi) {
    uint32_t r;
    asm("cvt.rn.bf16x2.f32 %0, %1, %2;" : "=r"(r) : "f"(hi), "f"(lo));
    return r;
}
__device__ __forceinline__ uint32_t pack_f16(float lo, float hi) {
    uint32_t r;
    asm("cvt.rn.f16x2.f32 %0, %1, %2;" : "=r"(r) : "f"(hi), "f"(lo));
    return r;
}
__device__ __forceinline__ uint32_t ex2_f16x2(uint32_t a) {
    uint32_t r;
    asm("ex2.approx.f16x2 %0, %1;" : "=r"(r) : "r"(a));
    return r;
}

// ---------------------------------------------------------------------------
// Prep (merged): blocks [0,3072) convert P fp32->bf16; blocks [3072,3840)
// transpose V basis (RxD fp32) -> VT (DxR bf16).
// ---------------------------------------------------------------------------
__global__ __launch_bounds__(256) void prep_kernel(
    const float* __restrict__ Pq, const float* __restrict__ Pk, const float* __restrict__ Pv,
    const float* __restrict__ Vq, const float* __restrict__ Vk, const float* __restrict__ Vv)
{
    __shared__ float t[32][33];
    const int bid = blockIdx.x;
    const int tid = threadIdx.x;

    if (bid < 3072) {
        const int sel = bid >> 10;
        const float* src = (sel == 0) ? Pq : (sel == 1) ? Pk : Pv;
        const int idx = (bid & 1023) * 256 + tid;
        float4 v = ((const float4*)src)[idx];
        uint2 o;
        o.x = pack_bf16(v.x, v.y);
        o.y = pack_bf16(v.z, v.w);
        ((uint2*)g_Pbf4)[(size_t)sel * 262144 + idx] = o;
    } else {
        const int b2  = bid - 3072;
        const int sel = b2 >> 8;
        const int rem = b2 & 255;
        const int d0  = (rem & 31) * 32;
        const int r0  = (rem >> 5) * 32;
        const float* src = (sel == 0) ? Vq : (sel == 1) ? Vk : Vv;
        __nv_bfloat16* dst = (__nv_bfloat16*)g_VT4p + (size_t)sel * D_ * R_;
        const int tx = tid & 31;
        const int ty = tid >> 5;
#pragma unroll
        for (int i = 0; i < 4; i++) {
            const int row = ty + i * 8;
            t[row][tx] = src[(size_t)(r0 + row) * D_ + d0 + tx];
        }
        __syncthreads();
#pragma unroll
        for (int i = 0; i < 4; i++) {
            const int drow = ty + i * 8;
            dst[(size_t)(d0 + drow) * R_ + r0 + tx] = __float2bfloat16(t[tx][drow]);
        }
    }
}

// ---------------------------------------------------------------------------
// Kernel 1: HMMA projection, 2 HEADS per CTA (128 rows x 128 cols), K=256 in
// 4 chunks, cp.async double-buffered. Halves P re-read traffic vs 1-head CTAs.
// ---------------------------------------------------------------------------
#define PJ_SA    0        // 2 x (128 x 128B) A double buffer (32768)
#define PJ_SB    32768    // 2 x (128 x 128B) B double buffer (32768)
#define PJ_BIAS  65536    // 128 floats
#define PJ_SMEM  66048    // v staging (64x132 floats = 33792B) aliases [0..)

__global__ __launch_bounds__(256) void proj_mma_kernel(
    const float* __restrict__ bq, const float* __restrict__ bk,
    const int* __restrict__ pos_ids)
{
    extern __shared__ __align__(1024) unsigned char smem[];
    const uint32_t sbase = smem_u32(smem);
    const int tid  = threadIdx.x;
    const int lane = tid & 31;
    const int w    = tid >> 5;
    const int lrow = lane & 15;
    const int lcol = lane >> 4;
    const int q2   = (lane & 3) * 2;

    const int bm0 = blockIdx.x * 128;
    const int hp  = blockIdx.y;        // head pair: heads 2hp, 2hp+1
    const int sel = blockIdx.z;
    const int b   = bm0 >> 10;
    const int mb  = bm0 & (M_ - 1);

    const uint4* pbase = g_Pbf4 + (size_t)sel * 131072 + (size_t)bm0 * 32;      // 32 uint4/row
    const uint4* vbase = g_VT4p + (size_t)sel * 32768 + (size_t)(hp * 128) * 32;

    // prologue: chunk 0 into buffer 0 (A: 1024 uint4, B: 1024 uint4)
    {
#pragma unroll
        for (int t = 0; t < 4; t++) {
            int idx = tid + t * 256;
            int rr = idx >> 3, c = idx & 7;
            CP_ASYNC16(sbase + PJ_SA + SWZ(rr * 128 + c * 16), pbase + rr * 32 + c);
            CP_ASYNC16(sbase + PJ_SB + SWZ(rr * 128 + c * 16), vbase + rr * 32 + c);
        }
        CP_COMMIT();
    }
    if (sel < 2 && tid < 128) {
        const float* bias = (sel == 0) ? bq : bk;
        ((float*)(smem + PJ_BIAS))[tid] = bias[hp * 128 + tid];
    }

    float C[16][4];
#pragma unroll
    for (int j = 0; j < 16; j++)
#pragma unroll
        for (int e = 0; e < 4; e++) C[j][e] = 0.0f;

#pragma unroll
    for (int k = 0; k < 4; k++) {
        CP_WAIT(0);
        __syncthreads();   // chunk k visible; all readers of target buffer done

        if (k < 3) {       // prefetch chunk k+1 into the other buffer
            const int kc = (k + 1) << 3;
            const uint32_t abuf = sbase + PJ_SA + ((k + 1) & 1) * 16384;
            const uint32_t bbuf = sbase + PJ_SB + ((k + 1) & 1) * 16384;
#pragma unroll
            for (int t = 0; t < 4; t++) {
                int idx = tid + t * 256;
                int rr = idx >> 3, c = idx & 7;
                CP_ASYNC16(abuf + SWZ(rr * 128 + c * 16), pbase + rr * 32 + kc + c);
                CP_ASYNC16(bbuf + SWZ(rr * 128 + c * 16), vbase + rr * 32 + kc + c);
            }
            CP_COMMIT();
        }

        const uint32_t abuf = sbase + PJ_SA + (k & 1) * 16384;
        const uint32_t bbuf = sbase + PJ_SB + (k & 1) * 16384;

        uint32_t af[4][4];
#pragma unroll
        for (int s = 0; s < 4; s++) {
            uint32_t a = abuf + SWZ((16 * w + lrow) * 128 + s * 32 + lcol * 16);
            LDMATRIX_X4(af[s][0], af[s][1], af[s][2], af[s][3], a);
        }
#pragma unroll
        for (int jj = 0; jj < 8; jj++) {
#pragma unroll
            for (int s = 0; s < 4; s++) {
                uint32_t b0, b1, b2, b3;
                uint32_t a = bbuf + SWZ((jj * 16 + lrow) * 128 + s * 32 + lcol * 16);
                LDMATRIX_X4(b0, b1, b2, b3, a);
                MMA_16816(C[2 * jj],     af[s], b0, b2);
                MMA_16816(C[2 * jj + 1], af[s], b1, b3);
            }
        }
    }

    const int row0 = 16 * w + (lane >> 2);
    const int row1 = row0 + 8;

    if (sel < 2) {
        const float qscale = (sel == 0) ? QSCALE : 1.0f;
        const float L2T = 13.287712379549449f / 32.0f;
        const float* sb = (const float*)(smem + PJ_BIAS);
        __nv_bfloat16* outb = (__nv_bfloat16*)(sel == 0 ? g_qbf4 : g_kbf4);
        const float pos0 = (float)pos_ids[b * M_ + mb + row0];
        const float pos1 = (float)pos_ids[b * M_ + mb + row1];
#pragma unroll
        for (int hh = 0; hh < 2; hh++) {
            const int h = 2 * hp + hh;
            const int bj = hh * 8;
            const size_t base0 = ((size_t)(b * H_ + h) * M_ + mb + row0) * DH_;
            const size_t base1 = ((size_t)(b * H_ + h) * M_ + mb + row1) * DH_;
#pragma unroll
            for (int j = 0; j < 4; j++) {
#pragma unroll
                for (int e = 0; e < 2; e++) {
                    const int dd0 = j * 8 + q2 + e;     // < 32
                    const float inv = exp2f(-(float)dd0 * L2T);
                    const float blo = sb[hh * 64 + dd0], bhi = sb[hh * 64 + dd0 + 32];
                    {
                        float sn, cs;
                        __sincosf(pos0 * inv, &sn, &cs);
                        const float x0 = C[bj + j][e] + blo, x1 = C[bj + j + 4][e] + bhi;
                        outb[base0 + dd0]      = __float2bfloat16((x0 * cs - x1 * sn) * qscale);
                        outb[base0 + dd0 + 32] = __float2bfloat16((x0 * sn + x1 * cs) * qscale);
                    }
                    {
                        float sn, cs;
                        __sincosf(pos1 * inv, &sn, &cs);
                        const float x0 = C[bj + j][e + 2] + blo, x1 = C[bj + j + 4][e + 2] + bhi;
                        outb[base1 + dd0]      = __float2bfloat16((x0 * cs - x1 * sn) * qscale);
                        outb[base1 + dd0 + 32] = __float2bfloat16((x0 * sn + x1 * cs) * qscale);
                    }
                }
            }
        }
    } else {
        // v: two passes (one per head): transpose-stage in smem, write f16 (b,h,d,m).
        float* sT = (float*)smem;
#pragma unroll
        for (int hh = 0; hh < 2; hh++) {
            const int h = 2 * hp + hh;
            __syncthreads();
#pragma unroll
            for (int j = 0; j < 8; j++) {
                const int col = j * 8 + q2;     // within-head d 0..63
                sT[col * 132 + row0]       = C[hh * 8 + j][0];
                sT[(col + 1) * 132 + row0] = C[hh * 8 + j][1];
                sT[col * 132 + row1]       = C[hh * 8 + j][2];
                sT[(col + 1) * 132 + row1] = C[hh * 8 + j][3];
            }
            __syncthreads();
#pragma unroll
            for (int t = 0; t < 4; t++) {
                int idx = tid + t * 256;       // 1024 uint4: 64 d-rows x 16 chunks
                int dd = idx >> 4, mc = idx & 15;
                const float* s = sT + dd * 132 + mc * 8;
                uint4 wv;
                wv.x = pack_f16(s[0], s[1]);
                wv.y = pack_f16(s[2], s[3]);
                wv.z = pack_f16(s[4], s[5]);
                wv.w = pack_f16(s[6], s[7]);
                g_vT4[((size_t)(b * H_ + h) * DH_ + dd) * (M_ / 8) + (mb >> 3) + mc] = wv;
            }
        }
    }
}

// ---------------------------------------------------------------------------
// Kernel 2: HMMA flash attention (R12 configuration — 8 warps, 256 threads).
// f16x2 SIMD exp2 softmax (output IS the PV A-fragment), PV in f16 MMA,
// tensor-core l-sum, 128-key super-tiles, depth-2 cp.async pipeline.
// ---------------------------------------------------------------------------
#define SQ_OFF    0        // 128 x 128B
#define SK_OFF    16384    // 2 bufs x (2 panels x 8192)
#define SV_OFF    49152    // 2 bufs x (2 panels x 8192)
#define SMASK_OFF 81920    // 1024 floats
#define SONES_OFF 86016    // 16 rows x 128B: row0 = f16 1.0, rest 0
#define SFLAG_OFF 88064    // 16 ints
#define SBIAS_OFF 88128    // 64 floats
#define ATTN_SMEM 88384

__global__ __launch_bounds__(256, 2) void attn_mma_kernel(
    const int* __restrict__ amask, const float* __restrict__ bv, float* __restrict__ out)
{
    extern __shared__ __align__(1024) unsigned char smem[];
    const uint32_t sbase = smem_u32(smem);
    const int tid  = threadIdx.x;
    const int lane = tid & 31;
    const int w    = tid >> 5;
    const int bh   = blockIdx.y;
    const int b    = bh >> 4;
    const int h    = bh & 15;
    const int m0   = blockIdx.x * 128;
    const int lrow = lane & 15;
    const int lcol = lane >> 4;
    const int q2   = (lane & 3) * 2;

    const uint4* kall = g_kbf4 + (size_t)bh * M_ * 8;
    const uint4* vall = g_vT4 + (size_t)bh * (DH_ * M_ / 8);
    float* mrow = (float*)(smem + SMASK_OFF);
    int* sflags = (int*)(smem + SFLAG_OFF);

    // Q tile + mask row + ones region + bias
    {
        const uint4* qsrc = g_qbf4 + (size_t)(bh * M_ + m0) * 8;
#pragma unroll
        for (int t = 0; t < 4; t++) {
            int idx = tid + t * 256;
            int rr = idx >> 3, c = idx & 7;
            *(uint4*)(smem + SQ_OFF + SWZ(rr * 128 + c * 16)) = qsrc[idx];
        }
#pragma unroll
        for (int t = 0; t < 4; t++) {
            int idx = tid + t * 256;
            mrow[idx] = amask[b * M_ + idx] ? 0.0f : -110.0f;
        }
#pragma unroll
        for (int t = 0; t < 2; t++) {
            int idx = tid + t * 256;            // 512 uint32
            ((uint32_t*)(smem + SONES_OFF))[idx] = (idx < 32) ? 0x3C003C00u : 0u;
        }
    }
    if (tid < 64) ((float*)(smem + SBIAS_OFF))[tid] = bv[h * 64 + tid];
    __syncthreads();   // mask visible for flag scan

    if (tid < 16) {
        int f = 0;
#pragma unroll 8
        for (int i = 0; i < 64; i++) f |= (mrow[tid * 64 + i] < 0.0f) ? 1 : 0;
        sflags[tid] = f;
    }

    // prologue: super-tile 0 into buffer 0
    {
#pragma unroll
        for (int t = 0; t < 4; t++) {
            int idx = tid + t * 256;
            int row = idx >> 3, c = idx & 7;
            uint32_t kdst = sbase + SK_OFF + (row >> 6) * 8192 + SWZ((row & 63) * 128 + c * 16);
            CP_ASYNC16(kdst, kall + idx);
            int rr = idx >> 4, cc = idx & 15;
            uint32_t vdst = sbase + SV_OFF + (cc >> 3) * 8192 + SWZ(rr * 128 + (cc & 7) * 16);
            CP_ASYNC16(vdst, vall + (size_t)rr * (M_ / 8) + cc);
        }
        CP_COMMIT();
    }
    __syncthreads();   // Q + ones + flags visible

    uint32_t qf[4][4];
#pragma unroll
    for (int s = 0; s < 4; s++) {
        uint32_t a = sbase + SQ_OFF + SWZ((16 * w + lrow) * 128 + s * 32 + lcol * 16);
        LDMATRIX_X4(qf[s][0], qf[s][1], qf[s][2], qf[s][3], a);
    }
    // constant ones B fragment (same for every k-step)
    uint32_t ob0, ob1, ob2, ob3;
    LDMATRIX_X4(ob0, ob1, ob2, ob3, sbase + SONES_OFF + SWZ(lrow * 128 + lcol * 16));

    float O[8][4];
#pragma unroll
    for (int j = 0; j < 8; j++)
#pragma unroll
        for (int e = 0; e < 4; e++) O[j][e] = 0.0f;
    float Lacc[4] = {0.0f, 0.0f, 0.0f, 0.0f};   // col0 = row-sum of P (exact fp32)

#pragma unroll 1
    for (int it = 0; it < 8; it++) {            // 8 super-tiles of 128 keys
        const int buf = it & 1;
        CP_WAIT(0);
        __syncthreads();

        if (it < 7) {
            const int n1 = (it + 1) * 128;
            const uint4* ksrc = kall + (size_t)n1 * 8;
            const uint4* vsrc = vall + (n1 >> 3);
            const uint32_t kb = sbase + SK_OFF + (buf ^ 1) * 16384;
            const uint32_t vb = sbase + SV_OFF + (buf ^ 1) * 16384;
#pragma unroll
            for (int t = 0; t < 4; t++) {
                int idx = tid + t * 256;
                int row = idx >> 3, c = idx & 7;
                CP_ASYNC16(kb + (row >> 6) * 8192 + SWZ((row & 63) * 128 + c * 16), ksrc + idx);
                int rr = idx >> 4, cc = idx & 15;
                CP_ASYNC16(vb + (cc >> 3) * 8192 + SWZ(rr * 128 + (cc & 7) * 16),
                           vsrc + (size_t)rr * (M_ / 8) + cc);
            }
            CP_COMMIT();
        }

#pragma unroll
        for (int p = 0; p < 2; p++) {
            const uint32_t skb = sbase + SK_OFF + buf * 16384 + p * 8192;
            const uint32_t svb = sbase + SV_OFF + buf * 16384 + p * 8192;
            const int tix = it * 2 + p;
            const int doMask = sflags[tix];
            const float* mf = mrow + tix * 64;

            uint32_t pa[4][4];
#pragma unroll
            for (int jj = 0; jj < 4; jj++) {
                float S0[4] = {0.0f, 0.0f, 0.0f, 0.0f};
                float S1[4] = {0.0f, 0.0f, 0.0f, 0.0f};
#pragma unroll
                for (int s = 0; s < 4; s++) {
                    uint32_t k0, k1, k2, k3;
                    uint32_t a = skb + SWZ((jj * 16 + lrow) * 128 + s * 32 + lcol * 16);
                    LDMATRIX_X4(k0, k1, k2, k3, a);
                    MMA_16816(S0, qf[s], k0, k2);
                    MMA_16816(S1, qf[s], k1, k3);
                }
                if (doMask) {
                    const float a0 = mf[jj * 16 + q2],      a1 = mf[jj * 16 + q2 + 1];
                    const float b0m = mf[jj * 16 + 8 + q2], b1m = mf[jj * 16 + 8 + q2 + 1];
                    S0[0] += a0; S0[1] += a1; S0[2] += a0; S0[3] += a1;
                    S1[0] += b0m; S1[1] += b1m; S1[2] += b0m; S1[3] += b1m;
                }
                // p = exp2(S) in f16x2 SIMD; result IS the f16 A-fragment
                pa[jj][0] = ex2_f16x2(pack_f16(S0[0], S0[1]));
                pa[jj][1] = ex2_f16x2(pack_f16(S0[2], S0[3]));
                pa[jj][2] = ex2_f16x2(pack_f16(S1[0], S1[1]));
                pa[jj][3] = ex2_f16x2(pack_f16(S1[2], S1[3]));
            }

            // l += P @ ones (tensor pipe, exact fp32): 4 MMAs
#pragma unroll
            for (int s = 0; s < 4; s++)
                MMA_16816_F16(Lacc, pa[s], ob0, ob2);

            // O += P @ V^T (f16 MMA)
#pragma unroll
            for (int jj = 0; jj < 4; jj++) {
#pragma unroll
                for (int s = 0; s < 4; s++) {
                    uint32_t v0, v1, v2, v3;
                    uint32_t a = svb + SWZ((jj * 16 + lrow) * 128 + s * 32 + lcol * 16);
                    LDMATRIX_X4(v0, v1, v2, v3, a);
                    MMA_16816_F16(O[2 * jj],     pa[s], v0, v2);
                    MMA_16816_F16(O[2 * jj + 1], pa[s], v1, v3);
                }
            }
        }
    }

    // ---- l broadcast (col 0 lives at quad-lane 0) + epilogue ----
    const float l0 = __shfl_sync(0xffffffffu, Lacc[0], 0, 4);
    const float l1 = __shfl_sync(0xffffffffu, Lacc[2], 0, 4);
    {
        const float* sb = (const float*)(smem + SBIAS_OFF);
        const float inv0 = 1.0f / l0;
        const float inv1 = 1.0f / l1;
        const int row0 = 16 * w + (lane >> 2);
        const int row1 = row0 + 8;
        float* o0 = out + ((size_t)bh * M_ + m0 + row0) * DH_;
        float* o1 = out + ((size_t)bh * M_ + m0 + row1) * DH_;
#pragma unroll
        for (int j = 0; j < 8; j++) {
            const int col = j * 8 + q2;
            float2 w0, w1;
            w0.x = O[j][0] * inv0 + sb[col];
            w0.y = O[j][1] * inv0 + sb[col + 1];
            w1.x = O[j][2] * inv1 + sb[col];
            w1.y = O[j][3] * inv1 + sb[col + 1];
            *(float2*)(o0 + col) = w0;
            *(float2*)(o1 + col) = w1;
        }
    }
}

// ---------------------------------------------------------------------------
extern "C" void kernel_launch(void* const* d_in, const int* in_sizes, int n_in,
                              void* d_out, int out_size) {
    const float* Pq = (const float*)d_in[0];
    const float* Pk = (const float*)d_in[1];
    const float* Pv = (const float*)d_in[2];
    const float* Vq = (const float*)d_in[3];
    const float* Vk = (const float*)d_in[4];
    const float* Vv = (const float*)d_in[5];
    const float* bq = (const float*)d_in[6];
    const float* bk = (const float*)d_in[7];
    const float* bv = (const float*)d_in[8];
    const int* amask = (const int*)d_in[9];
    const int* pos   = (const int*)d_in[10];
    float* out = (float*)d_out;

    prep_kernel<<<3840, 256>>>(Pq, Pk, Pv, Vq, Vk, Vv);

    cudaFuncSetAttribute(proj_mma_kernel, cudaFuncAttributeMaxDynamicSharedMemorySize, PJ_SMEM);
    dim3 g1((B_ * M_) / 128, H_ / 2, 3);   // (32, 8, 3)
    proj_mma_kernel<<<g1, 256, PJ_SMEM>>>(bq, bk, pos);

    cudaFuncSetAttribute(attn_mma_kernel, cudaFuncAttributeMaxDynamicSharedMemorySize, ATTN_SMEM);
    dim3 g2(M_ / 128, B_ * H_);            // (8, 64)
    attn_mma_kernel<<<g2, 256, ATTN_SMEM>>>(amask, bv, out);
}

// round 16
// speedup vs baseline: 1.0644x; 1.0644x over previous
#include <cuda_runtime.h>
#include <cuda_bf16.h>
#include <math.h>
#include <stdint.h>

#define B_  4
#define M_  1024
#define R_  256
#define H_  16
#define DH_ 64
#define D_  1024   // H_*DH_

// q scale folds 1/sqrt(DH) AND log2(e) (softmax computed in exp2 domain)
#define QSCALE 0.18033688011112042f   // 0.125 * log2(e)

// q,k: bf16 (b,h,m,d) bias+RoPE applied (q prescaled by QSCALE).
// v: f16 (b,h,d,m) TRANSPOSED, NO bias (added exactly in attn epilogue).
__device__ uint4 g_qbf4[(size_t)B_ * H_ * M_ * DH_ / 8];
__device__ uint4 g_kbf4[(size_t)B_ * H_ * M_ * DH_ / 8];
__device__ uint4 g_vT4 [(size_t)B_ * H_ * DH_ * M_ / 8];
// prep buffers: P in bf16, V basis transposed to [d][r] bf16
__device__ uint4 g_Pbf4[(size_t)3 * B_ * M_ * R_ / 8];
__device__ uint4 g_VT4p[(size_t)3 * D_ * R_ / 8];

__device__ __forceinline__ uint32_t smem_u32(const void* p) {
    uint32_t a;
    asm("{ .reg .u64 t; cvta.to.shared.u64 t, %1; cvt.u32.u64 %0, t; }" : "=r"(a) : "l"(p));
    return a;
}
#define SWZ(x) ((x) ^ (((x) >> 3) & 0x70))

#define LDMATRIX_X4(r0, r1, r2, r3, addr) \
    asm volatile("ldmatrix.sync.aligned.m8n8.x4.shared.b16 {%0,%1,%2,%3}, [%4];" \
                 : "=r"(r0), "=r"(r1), "=r"(r2), "=r"(r3) : "r"(addr))

#define MMA_16816(d, a, b0, b1) \
    asm volatile("mma.sync.aligned.m16n8k16.row.col.f32.bf16.bf16.f32 " \
                 "{%0,%1,%2,%3}, {%4,%5,%6,%7}, {%8,%9}, {%0,%1,%2,%3};" \
                 : "+f"((d)[0]), "+f"((d)[1]), "+f"((d)[2]), "+f"((d)[3]) \
                 : "r"((a)[0]), "r"((a)[1]), "r"((a)[2]), "r"((a)[3]), "r"(b0), "r"(b1))

#define MMA_16816_F16(d, a, b0, b1) \
    asm volatile("mma.sync.aligned.m16n8k16.row.col.f32.f16.f16.f32 " \
                 "{%0,%1,%2,%3}, {%4,%5,%6,%7}, {%8,%9}, {%0,%1,%2,%3};" \
                 : "+f"((d)[0]), "+f"((d)[1]), "+f"((d)[2]), "+f"((d)[3]) \
                 : "r"((a)[0]), "r"((a)[1]), "r"((a)[2]), "r"((a)[3]), "r"(b0), "r"(b1))

#define CP_ASYNC16(dst, src) \
    asm volatile("cp.async.cg.shared.global [%0], [%1], 16;" :: "r"(dst), "l"(src))
#define CP_COMMIT()  asm volatile("cp.async.commit_group;" ::: "memory")
#define CP_WAIT(n)   asm volatile("cp.async.wait_group %0;" :: "n"(n) : "memory")

__device__ __forceinline__ uint32_t pack_bf16(float lo, float hi) {
    uint32_t r;
    asm("cvt.rn.bf16x2.f32 %0, %1, %2;" : "=r"(r) : "f"(hi), "f"(lo));
    return r;
}
__device__ __forceinline__ uint32_t pack_f16(float lo, float hi) {
    uint32_t r;
    asm("cvt.rn.f16x2.f32 %0, %1, %2;" : "=r"(r) : "f"(hi), "f"(lo));
    return r;
}
__device__ __forceinline__ uint32_t ex2_f16x2(uint32_t a) {
    uint32_t r;
    asm("ex2.approx.f16x2 %0, %1;" : "=r"(r) : "r"(a));
    return r;
}

// ---------------------------------------------------------------------------
// Prep (merged): blocks [0,3072) convert P fp32->bf16; blocks [3072,3840)
// transpose V basis (RxD fp32) -> VT (DxR bf16).
// ---------------------------------------------------------------------------
__global__ __launch_bounds__(256) void prep_kernel(
    const float* __restrict__ Pq, const float* __restrict__ Pk, const float* __restrict__ Pv,
    const float* __restrict__ Vq, const float* __restrict__ Vk, const float* __restrict__ Vv)
{
    __shared__ float t[32][33];
    const int bid = blockIdx.x;
    const int tid = threadIdx.x;

    if (bid < 3072) {
        const int sel = bid >> 10;
        const float* src = (sel == 0) ? Pq : (sel == 1) ? Pk : Pv;
        const int idx = (bid & 1023) * 256 + tid;
        float4 v = ((const float4*)src)[idx];
        uint2 o;
        o.x = pack_bf16(v.x, v.y);
        o.y = pack_bf16(v.z, v.w);
        ((uint2*)g_Pbf4)[(size_t)sel * 262144 + idx] = o;
    } else {
        const int b2  = bid - 3072;
        const int sel = b2 >> 8;
        const int rem = b2 & 255;
        const int d0  = (rem & 31) * 32;
        const int r0  = (rem >> 5) * 32;
        const float* src = (sel == 0) ? Vq : (sel == 1) ? Vk : Vv;
        __nv_bfloat16* dst = (__nv_bfloat16*)g_VT4p + (size_t)sel * D_ * R_;
        const int tx = tid & 31;
        const int ty = tid >> 5;
#pragma unroll
        for (int i = 0; i < 4; i++) {
            const int row = ty + i * 8;
            t[row][tx] = src[(size_t)(r0 + row) * D_ + d0 + tx];
        }
        __syncthreads();
#pragma unroll
        for (int i = 0; i < 4; i++) {
            const int drow = ty + i * 8;
            dst[(size_t)(d0 + drow) * R_ + r0 + tx] = __float2bfloat16(t[tx][drow]);
        }
    }
}

// ---------------------------------------------------------------------------
// Kernel 1: HMMA projection (R12/R9 structure, 64-col CTA — validated optimum).
// ---------------------------------------------------------------------------
#define PJ_SA    0        // 2 x (128 x 128B) A double buffer
#define PJ_SB    32768    // 2 x (64 x 128B)  B double buffer
#define PJ_BIAS  49152    // 64 floats
#define PJ_SMEM  49408    // v staging (64x132 floats) aliases [0..33792)

__global__ __launch_bounds__(256) void proj_mma_kernel(
    const float* __restrict__ bq, const float* __restrict__ bk,
    const int* __restrict__ pos_ids)
{
    __shared__ __align__(1024) unsigned char smem[PJ_SMEM];
    const uint32_t sbase = smem_u32(smem);
    const int tid  = threadIdx.x;
    const int lane = tid & 31;
    const int w    = tid >> 5;
    const int lrow = lane & 15;
    const int lcol = lane >> 4;
    const int q2   = (lane & 3) * 2;

    const int bm0 = blockIdx.x * 128;
    const int h   = blockIdx.y;
    const int sel = blockIdx.z;
    const int b   = bm0 >> 10;
    const int mb  = bm0 & (M_ - 1);

    const uint4* pbase = g_Pbf4 + (size_t)sel * 131072 + (size_t)bm0 * 32;
    const uint4* vbase = g_VT4p + (size_t)sel * 32768 + (size_t)(h * 64) * 32;

    {
#pragma unroll
        for (int t = 0; t < 4; t++) {
            int idx = tid + t * 256;
            int rr = idx >> 3, c = idx & 7;
            CP_ASYNC16(sbase + PJ_SA + SWZ(rr * 128 + c * 16), pbase + rr * 32 + c);
        }
#pragma unroll
        for (int t = 0; t < 2; t++) {
            int idx = tid + t * 256;
            int rr = idx >> 3, c = idx & 7;
            CP_ASYNC16(sbase + PJ_SB + SWZ(rr * 128 + c * 16), vbase + rr * 32 + c);
        }
        CP_COMMIT();
    }
    if (sel < 2 && tid < 64) {
        const float* bias = (sel == 0) ? bq : bk;
        ((float*)(smem + PJ_BIAS))[tid] = bias[h * 64 + tid];
    }

    float C[8][4];
#pragma unroll
    for (int j = 0; j < 8; j++)
#pragma unroll
        for (int e = 0; e < 4; e++) C[j][e] = 0.0f;

#pragma unroll
    for (int k = 0; k < 4; k++) {
        CP_WAIT(0);
        __syncthreads();

        if (k < 3) {
            const int kc = (k + 1) << 3;
            const uint32_t abuf = sbase + PJ_SA + ((k + 1) & 1) * 16384;
            const uint32_t bbuf = sbase + PJ_SB + ((k + 1) & 1) * 8192;
#pragma unroll
            for (int t = 0; t < 4; t++) {
                int idx = tid + t * 256;
                int rr = idx >> 3, c = idx & 7;
                CP_ASYNC16(abuf + SWZ(rr * 128 + c * 16), pbase + rr * 32 + kc + c);
            }
#pragma unroll
            for (int t = 0; t < 2; t++) {
                int idx = tid + t * 256;
                int rr = idx >> 3, c = idx & 7;
                CP_ASYNC16(bbuf + SWZ(rr * 128 + c * 16), vbase + rr * 32 + kc + c);
            }
            CP_COMMIT();
        }

        const uint32_t abuf = sbase + PJ_SA + (k & 1) * 16384;
        const uint32_t bbuf = sbase + PJ_SB + (k & 1) * 8192;

        uint32_t af[4][4];
#pragma unroll
        for (int s = 0; s < 4; s++) {
            uint32_t a = abuf + SWZ((16 * w + lrow) * 128 + s * 32 + lcol * 16);
            LDMATRIX_X4(af[s][0], af[s][1], af[s][2], af[s][3], a);
        }
#pragma unroll
        for (int jj = 0; jj < 4; jj++) {
#pragma unroll
            for (int s = 0; s < 4; s++) {
                uint32_t b0, b1, b2, b3;
                uint32_t a = bbuf + SWZ((jj * 16 + lrow) * 128 + s * 32 + lcol * 16);
                LDMATRIX_X4(b0, b1, b2, b3, a);
                MMA_16816(C[2 * jj],     af[s], b0, b2);
                MMA_16816(C[2 * jj + 1], af[s], b1, b3);
            }
        }
    }

    const int row0 = 16 * w + (lane >> 2);
    const int row1 = row0 + 8;

    if (sel < 2) {
        const float qscale = (sel == 0) ? QSCALE : 1.0f;
        const float L2T = 13.287712379549449f / 32.0f;
        const float* sb = (const float*)(smem + PJ_BIAS);
        __nv_bfloat16* outb = (__nv_bfloat16*)(sel == 0 ? g_qbf4 : g_kbf4);
        const float pos0 = (float)pos_ids[b * M_ + mb + row0];
        const float pos1 = (float)pos_ids[b * M_ + mb + row1];
        const size_t base0 = ((size_t)(b * H_ + h) * M_ + mb + row0) * DH_;
        const size_t base1 = ((size_t)(b * H_ + h) * M_ + mb + row1) * DH_;
#pragma unroll
        for (int j = 0; j < 4; j++) {
#pragma unroll
            for (int e = 0; e < 2; e++) {
                const int dd0 = j * 8 + q2 + e;     // < 32
                const float inv = exp2f(-(float)dd0 * L2T);
                const float blo = sb[dd0], bhi = sb[dd0 + 32];
                {
                    float sn, cs;
                    __sincosf(pos0 * inv, &sn, &cs);
                    const float x0 = C[j][e] + blo, x1 = C[j + 4][e] + bhi;
                    outb[base0 + dd0]      = __float2bfloat16((x0 * cs - x1 * sn) * qscale);
                    outb[base0 + dd0 + 32] = __float2bfloat16((x0 * sn + x1 * cs) * qscale);
                }
                {
                    float sn, cs;
                    __sincosf(pos1 * inv, &sn, &cs);
                    const float x0 = C[j][e + 2] + blo, x1 = C[j + 4][e + 2] + bhi;
                    outb[base1 + dd0]      = __float2bfloat16((x0 * cs - x1 * sn) * qscale);
                    outb[base1 + dd0 + 32] = __float2bfloat16((x0 * sn + x1 * cs) * qscale);
                }
            }
        }
    } else {
        __syncthreads();
        float* sT = (float*)smem;
#pragma unroll
        for (int j = 0; j < 8; j++) {
            const int col = j * 8 + q2;
            sT[col * 132 + row0]       = C[j][0];
            sT[(col + 1) * 132 + row0] = C[j][1];
            sT[col * 132 + row1]       = C[j][2];
            sT[(col + 1) * 132 + row1] = C[j][3];
        }
        __syncthreads();
#pragma unroll
        for (int t = 0; t < 4; t++) {
            int idx = tid + t * 256;
            int dd = idx >> 4, mc = idx & 15;
            const float* s = sT + dd * 132 + mc * 8;
            uint4 wv;
            wv.x = pack_f16(s[0], s[1]);
            wv.y = pack_f16(s[2], s[3]);
            wv.z = pack_f16(s[4], s[5]);
            wv.w = pack_f16(s[6], s[7]);
            g_vT4[((size_t)(b * H_ + h) * DH_ + dd) * (M_ / 8) + (mb >> 3) + mc] = wv;
        }
    }
}

// ---------------------------------------------------------------------------
// Kernel 2: HMMA flash attention (R12 shape: 8 warps, 256 threads) with
// KEY-BLOCK SOFTWARE PIPELINING: per 16-key block, QK -> exp2/pack -> L-MMA
// -> PV immediately, so next block's QK overlaps this block's MUFU chain.
// f16x2 exp2 softmax, tensor-core l-sum, 128-key super-tiles, depth-2 cp.async.
// ---------------------------------------------------------------------------
#define SQ_OFF    0        // 128 x 128B
#define SK_OFF    16384    // 2 bufs x (2 panels x 8192)
#define SV_OFF    49152    // 2 bufs x (2 panels x 8192)
#define SMASK_OFF 81920    // 1024 floats
#define SONES_OFF 86016    // 16 rows x 128B: row0 = f16 1.0, rest 0
#define SFLAG_OFF 88064    // 16 ints
#define SBIAS_OFF 88128    // 64 floats
#define ATTN_SMEM 88384

__global__ __launch_bounds__(256, 2) void attn_mma_kernel(
    const int* __restrict__ amask, const float* __restrict__ bv, float* __restrict__ out)
{
    extern __shared__ __align__(1024) unsigned char smem[];
    const uint32_t sbase = smem_u32(smem);
    const int tid  = threadIdx.x;
    const int lane = tid & 31;
    const int w    = tid >> 5;
    const int bh   = blockIdx.y;
    const int b    = bh >> 4;
    const int h    = bh & 15;
    const int m0   = blockIdx.x * 128;
    const int lrow = lane & 15;
    const int lcol = lane >> 4;
    const int q2   = (lane & 3) * 2;

    const uint4* kall = g_kbf4 + (size_t)bh * M_ * 8;
    const uint4* vall = g_vT4 + (size_t)bh * (DH_ * M_ / 8);
    float* mrow = (float*)(smem + SMASK_OFF);
    int* sflags = (int*)(smem + SFLAG_OFF);

    // Q tile + mask row + ones region + bias
    {
        const uint4* qsrc = g_qbf4 + (size_t)(bh * M_ + m0) * 8;
#pragma unroll
        for (int t = 0; t < 4; t++) {
            int idx = tid + t * 256;
            int rr = idx >> 3, c = idx & 7;
            *(uint4*)(smem + SQ_OFF + SWZ(rr * 128 + c * 16)) = qsrc[idx];
        }
#pragma unroll
        for (int t = 0; t < 4; t++) {
            int idx = tid + t * 256;
            mrow[idx] = amask[b * M_ + idx] ? 0.0f : -110.0f;
        }
#pragma unroll
        for (int t = 0; t < 2; t++) {
            int idx = tid + t * 256;            // 512 uint32
            ((uint32_t*)(smem + SONES_OFF))[idx] = (idx < 32) ? 0x3C003C00u : 0u;
        }
    }
    if (tid < 64) ((float*)(smem + SBIAS_OFF))[tid] = bv[h * 64 + tid];
    __syncthreads();   // mask visible for flag scan

    if (tid < 16) {
        int f = 0;
#pragma unroll 8
        for (int i = 0; i < 64; i++) f |= (mrow[tid * 64 + i] < 0.0f) ? 1 : 0;
        sflags[tid] = f;
    }

    // prologue: super-tile 0 into buffer 0
    {
#pragma unroll
        for (int t = 0; t < 4; t++) {
            int idx = tid + t * 256;
            int row = idx >> 3, c = idx & 7;
            uint32_t kdst = sbase + SK_OFF + (row >> 6) * 8192 + SWZ((row & 63) * 128 + c * 16);
            CP_ASYNC16(kdst, kall + idx);
            int rr = idx >> 4, cc = idx & 15;
            uint32_t vdst = sbase + SV_OFF + (cc >> 3) * 8192 + SWZ(rr * 128 + (cc & 7) * 16);
            CP_ASYNC16(vdst, vall + (size_t)rr * (M_ / 8) + cc);
        }
        CP_COMMIT();
    }
    __syncthreads();   // Q + ones + flags visible

    uint32_t qf[4][4];
#pragma unroll
    for (int s = 0; s < 4; s++) {
        uint32_t a = sbase + SQ_OFF + SWZ((16 * w + lrow) * 128 + s * 32 + lcol * 16);
        LDMATRIX_X4(qf[s][0], qf[s][1], qf[s][2], qf[s][3], a);
    }
    // constant ones B fragment (same for every k-step)
    uint32_t ob0, ob1, ob2, ob3;
    LDMATRIX_X4(ob0, ob1, ob2, ob3, sbase + SONES_OFF + SWZ(lrow * 128 + lcol * 16));

    float O[8][4];
#pragma unroll
    for (int j = 0; j < 8; j++)
#pragma unroll
        for (int e = 0; e < 4; e++) O[j][e] = 0.0f;
    float Lacc[4] = {0.0f, 0.0f, 0.0f, 0.0f};   // col0 = row-sum of P (exact fp32)

#pragma unroll 1
    for (int it = 0; it < 8; it++) {            // 8 super-tiles of 128 keys
        const int buf = it & 1;
        CP_WAIT(0);
        __syncthreads();

        if (it < 7) {
            const int n1 = (it + 1) * 128;
            const uint4* ksrc = kall + (size_t)n1 * 8;
            const uint4* vsrc = vall + (n1 >> 3);
            const uint32_t kb2 = sbase + SK_OFF + (buf ^ 1) * 16384;
            const uint32_t vb2 = sbase + SV_OFF + (buf ^ 1) * 16384;
#pragma unroll
            for (int t = 0; t < 4; t++) {
                int idx = tid + t * 256;
                int row = idx >> 3, c = idx & 7;
                CP_ASYNC16(kb2 + (row >> 6) * 8192 + SWZ((row & 63) * 128 + c * 16), ksrc + idx);
                int rr = idx >> 4, cc = idx & 15;
                CP_ASYNC16(vb2 + (cc >> 3) * 8192 + SWZ(rr * 128 + (cc & 7) * 16),
                           vsrc + (size_t)rr * (M_ / 8) + cc);
            }
            CP_COMMIT();
        }

#pragma unroll
        for (int p = 0; p < 2; p++) {
            const uint32_t skb = sbase + SK_OFF + buf * 16384 + p * 8192;
            const uint32_t svb = sbase + SV_OFF + buf * 16384 + p * 8192;
            const int tix = it * 2 + p;
            const int doMask = sflags[tix];
            const float* mf = mrow + tix * 64;

            // key-block-pipelined: QK(kb) -> exp2 -> L -> PV(kb), then next kb
#pragma unroll
            for (int kb = 0; kb < 4; kb++) {
                float S0[4] = {0.0f, 0.0f, 0.0f, 0.0f};
                float S1[4] = {0.0f, 0.0f, 0.0f, 0.0f};
#pragma unroll
                for (int s = 0; s < 4; s++) {
                    uint32_t k0, k1, k2, k3;
                    uint32_t a = skb + SWZ((kb * 16 + lrow) * 128 + s * 32 + lcol * 16);
                    LDMATRIX_X4(k0, k1, k2, k3, a);
                    MMA_16816(S0, qf[s], k0, k2);
                    MMA_16816(S1, qf[s], k1, k3);
                }
                if (doMask) {
                    const float a0 = mf[kb * 16 + q2],      a1 = mf[kb * 16 + q2 + 1];
                    const float b0m = mf[kb * 16 + 8 + q2], b1m = mf[kb * 16 + 8 + q2 + 1];
                    S0[0] += a0; S0[1] += a1; S0[2] += a0; S0[3] += a1;
                    S1[0] += b0m; S1[1] += b1m; S1[2] += b0m; S1[3] += b1m;
                }
                uint32_t pa[4];
                pa[0] = ex2_f16x2(pack_f16(S0[0], S0[1]));
                pa[1] = ex2_f16x2(pack_f16(S0[2], S0[3]));
                pa[2] = ex2_f16x2(pack_f16(S1[0], S1[1]));
                pa[3] = ex2_f16x2(pack_f16(S1[2], S1[3]));

                // l += P_kb @ ones
                MMA_16816_F16(Lacc, pa, ob0, ob2);

                // O += P_kb @ V^T_kb  (K-dim = this key block)
#pragma unroll
                for (int jj = 0; jj < 4; jj++) {
                    uint32_t v0, v1, v2, v3;
                    uint32_t a = svb + SWZ((jj * 16 + lrow) * 128 + kb * 32 + lcol * 16);
                    LDMATRIX_X4(v0, v1, v2, v3, a);
                    MMA_16816_F16(O[2 * jj],     pa, v0, v2);
                    MMA_16816_F16(O[2 * jj + 1], pa, v1, v3);
                }
            }
        }
    }

    // ---- l broadcast (col 0 lives at quad-lane 0) + epilogue ----
    const float l0 = __shfl_sync(0xffffffffu, Lacc[0], 0, 4);
    const float l1 = __shfl_sync(0xffffffffu, Lacc[2], 0, 4);
    {
        const float* sb = (const float*)(smem + SBIAS_OFF);
        const float inv0 = 1.0f / l0;
        const float inv1 = 1.0f / l1;
        const int row0 = 16 * w + (lane >> 2);
        const int row1 = row0 + 8;
        float* o0 = out + ((size_t)bh * M_ + m0 + row0) * DH_;
        float* o1 = out + ((size_t)bh * M_ + m0 + row1) * DH_;
#pragma unroll
        for (int j = 0; j < 8; j++) {
            const int col = j * 8 + q2;
            float2 w0, w1;
            w0.x = O[j][0] * inv0 + sb[col];
            w0.y = O[j][1] * inv0 + sb[col + 1];
            w1.x = O[j][2] * inv1 + sb[col];
            w1.y = O[j][3] * inv1 + sb[col + 1];
            *(float2*)(o0 + col) = w0;
            *(float2*)(o1 + col) = w1;
        }
    }
}

// ---------------------------------------------------------------------------
extern "C" void kernel_launch(void* const* d_in, const int* in_sizes, int n_in,
                              void* d_out, int out_size) {
    const float* Pq = (const float*)d_in[0];
    const float* Pk = (const float*)d_in[1];
    const float* Pv = (const float*)d_in[2];
    const float* Vq = (const float*)d_in[3];
    const float* Vk = (const float*)d_in[4];
    const float* Vv = (const float*)d_in[5];
    const float* bq = (const float*)d_in[6];
    const float* bk = (const float*)d_in[7];
    const float* bv = (const float*)d_in[8];
    const int* amask = (const int*)d_in[9];
    const int* pos   = (const int*)d_in[10];
    float* out = (float*)d_out;

    prep_kernel<<<3840, 256>>>(Pq, Pk, Pv, Vq, Vk, Vv);

    dim3 g1((B_ * M_) / 128, H_, 3);       // (32, 16, 3)
    proj_mma_kernel<<<g1, 256>>>(bq, bk, pos);

    cudaFuncSetAttribute(attn_mma_kernel, cudaFuncAttributeMaxDynamicSharedMemorySize, ATTN_SMEM);
    dim3 g2(M_ / 128, B_ * H_);            // (8, 64)
    attn_mma_kernel<<<g2, 256, ATTN_SMEM>>>(amask, bv, out);
}